// round 2
// baseline (speedup 1.0000x reference)
#include <cuda_runtime.h>
#include <math_constants.h>

// LogcumsumexpOp: out = inclusive scan of logaddexp along axis 1 of x[8,4096,1024] fp32.
//
// Layout: x[(b*T + t)*C + c], channel axis contiguous.
// Grid: one block per (batch, 32-channel tile) = 8*32 = 256 blocks, 256 threads.
// Block layout: tid = c_local + 32*w, w in [0,8). Each iteration processes a
// slab of W*S = 128 t-rows; thread (c,w) owns S=16 consecutive rows in regs.
// Per slab: per-thread logsumexp reduce -> warp-0 serial exclusive scan of the
// 8 chunk totals (+ cross-slab carry) -> seeded serial logaddexp scan over the
// register values -> coalesced store. Next slab double-buffer prefetched.

#define BB 8
#define TT 4096
#define CC 1024
#define CT 32              // channels per block
#define W  8               // sub-chunks (warps) per slab
#define S  16              // serial elements per thread per slab
#define SLAB (W * S)       // 128 rows per iteration
#define NITER (TT / SLAB)  // 32

__device__ __forceinline__ float laddexp(float a, float b) {
    // max(a,b) + log(1 + exp(-|a-b|)); safe for exactly one operand == -inf.
    float m = fmaxf(a, b);
    float d = -fabsf(a - b);
    return m + __logf(1.0f + __expf(d));
}

__global__ void __launch_bounds__(256, 2)
lcse_kernel(const float* __restrict__ x, float* __restrict__ out) {
    const int b     = blockIdx.x >> 5;   // 256 blocks: b = idx/32
    const int ctile = blockIdx.x & 31;   // channel tile
    const int lc    = threadIdx.x & 31;  // channel lane within tile
    const int w     = threadIdx.x >> 5;  // sub-chunk index (== warp id)
    const int c     = ctile * CT + lc;

    __shared__ float sm_v[W][CT];  // chunk totals
    __shared__ float sm_p[W][CT];  // exclusive prefixes

    const float* __restrict__ xp = x   + (size_t)b * TT * CC + c;
    float*       __restrict__ op = out + (size_t)b * TT * CC + c;

    float carry = -CUDART_INF_F;   // meaningful only in warp 0 (per-channel carry)

    float va[S], vb[S];

    // Preload slab 0 (coalesced: warp = 32 consecutive channels per row).
    {
        const int t0 = w * S;
        #pragma unroll
        for (int k = 0; k < S; k++)
            va[k] = xp[(size_t)(t0 + k) * CC];
    }

    for (int it = 0; it < NITER; it++) {
        const int base = it * SLAB + w * S;

        // ---- Phase 1: chunk logsumexp of the S register values (cheap chain:
        //       fmax tree + independent EX2s + FADD accumulate + one LG2).
        float m = va[0];
        #pragma unroll
        for (int k = 1; k < S; k++) m = fmaxf(m, va[k]);
        float ssum = 0.0f;
        #pragma unroll
        for (int k = 0; k < S; k++) ssum += __expf(va[k] - m);
        const float cv = m + __logf(ssum);

        sm_v[w][lc] = cv;
        __syncthreads();

        // ---- Prefetch next slab while the scan + seeded pass run.
        if (it + 1 < NITER) {
            const int nb = (it + 1) * SLAB + w * S;
            #pragma unroll
            for (int k = 0; k < S; k++)
                vb[k] = xp[(size_t)(nb + k) * CC];
        }

        // ---- Phase 2: warp 0 serially scans the 8 chunk totals per channel,
        //       seeded with the cross-slab carry; writes exclusive prefixes.
        if (w == 0) {
            float pre = carry;
            #pragma unroll
            for (int j = 0; j < W; j++) {
                sm_p[j][lc] = pre;
                pre = laddexp(pre, sm_v[j][lc]);
            }
            carry = pre;  // inclusive total of this slab -> carry for next
        }
        __syncthreads();

        // ---- Phase 3: seeded serial logaddexp scan over register values.
        float acc = sm_p[w][lc];
        #pragma unroll
        for (int k = 0; k < S; k++) {
            acc = laddexp(acc, va[k]);
            op[(size_t)(base + k) * CC] = acc;
        }

        // Rotate double buffer (compiles to register renaming / MOVs).
        #pragma unroll
        for (int k = 0; k < S; k++) va[k] = vb[k];
        // No trailing barrier needed: next iteration's first __syncthreads()
        // (after the sm_v writes) orders this iteration's sm_p reads against
        // warp 0's next sm_p writes.
    }
}

extern "C" void kernel_launch(void* const* d_in, const int* in_sizes, int n_in,
                              void* d_out, int out_size) {
    const float* x = (const float*)d_in[0];
    float* out = (float*)d_out;
    (void)in_sizes; (void)n_in; (void)out_size;

    dim3 grid(BB * (CC / CT));  // 256 blocks
    dim3 block(CT * W);         // 256 threads
    lcse_kernel<<<grid, block>>>(x, out);
}

// round 5
// speedup vs baseline: 1.5136x; 1.5136x over previous
#include <cuda_runtime.h>
#include <math_constants.h>

// LogcumsumexpOp: inclusive logaddexp scan along axis 1 of x[8,4096,1024] fp32.
//
// Single-pass chained segmented scan:
//   256 chains = (batch, 32-channel tile). Each chain split into NSEG=32
//   segments of SEG_T=128 rows -> 8192 blocks of 256 threads (8 warps x 32 ch).
//   Grid is seg-major (blockIdx = seg*NCHAINS + chain) so a segment's
//   predecessor always has a smaller blockIdx (scheduled no later).
//
// Per block:
//   phase1: each thread owns 16 rows of one channel; computes chunk max m,
//           e[k]=exp(v-m) with in-register inclusive cumsum S_k, chunk total
//           cv = m + log(S_15) -> smem.
//   phase2: warp 0 scans the 8 chunk totals per channel in exp domain,
//           spin-waits on the predecessor segment's published 8B
//           {inclusive, flag} word, folds it in, publishes its own inclusive,
//           writes per-chunk log-domain exclusive prefixes to smem.
//   phase3: out_k = M2 + log(Ea + Eb*S_k): one independent LG2+FFMA per
//           element (no serial laddexp chain), coalesced streaming store.
//
// Flag state lives in a __device__ global; a tiny init kernel zeroes it at
// the start of every launch (graph-replay safe; same-stream ordering).

#define BB 8
#define TT 4096
#define CC 1024
#define CT 32                    // channels per chain
#define NW 8                     // warps per block
#define SROWS 16                 // rows per thread
#define SEG_T (NW * SROWS)       // 128 rows per segment
#define NSEG (TT / SEG_T)        // 32 segments per chain
#define NCHAINS (BB * (CC / CT)) // 256 chains
#define NBLK (NCHAINS * NSEG)    // 8192 blocks
#define NSLOT (NCHAINS * NSEG * CT)

// One 8-byte word per (chain, seg, channel-lane): low 32 = float bits of the
// inclusive prefix, high 32 = nonzero flag. Single 8B store => atomic publish.
__device__ unsigned long long g_slot[NSLOT];

__global__ void zero_slots_kernel() {
    unsigned i = blockIdx.x * blockDim.x + threadIdx.x;
    if (i < NSLOT) g_slot[i] = 0ULL;
}

__device__ __forceinline__ unsigned long long poll_cg(
    const unsigned long long* p) {
    unsigned long long u;
    asm volatile("ld.global.cg.b64 %0, [%1];" : "=l"(u) : "l"(p) : "memory");
    return u;
}

__global__ void __launch_bounds__(256, 4)
lcse_seg_kernel(const float* __restrict__ x, float* __restrict__ out) {
    const int seg   = blockIdx.x / NCHAINS;   // seg-major ordering
    const int chain = blockIdx.x % NCHAINS;
    const int b     = chain >> 5;
    const int ctile = chain & 31;
    const int lc    = threadIdx.x & 31;       // channel lane
    const int w     = threadIdx.x >> 5;       // chunk (warp) index
    const int c     = ctile * CT + lc;

    __shared__ float sm_v[NW][CT];  // per-chunk logsumexp totals
    __shared__ float sm_p[NW][CT];  // per-chunk log-domain exclusive prefixes

    const size_t row0 = (size_t)b * TT + (size_t)seg * SEG_T + (size_t)w * SROWS;
    const float* __restrict__ xp = x   + row0 * CC + c;
    float*       __restrict__ op = out + row0 * CC + c;

    const unsigned long long* pred_slot =
        (seg > 0) ? &g_slot[((size_t)chain * NSEG + (seg - 1)) * CT + lc]
                  : (const unsigned long long*)0;

    // ---- Load 16 rows (coalesced 128B per warp-row), streaming hint.
    float v[SROWS];
    #pragma unroll
    for (int k = 0; k < SROWS; k++)
        v[k] = __ldcs(xp + (size_t)k * CC);

    // Early non-blocking probe: warm the predecessor slot line / often grabs
    // the already-set flag so phase 2's spin hits the fast path.
    unsigned long long early = 0ULL;
    if (w == 0 && seg > 0) early = poll_cg(pred_slot);

    // ---- Phase 1: chunk max, exp, in-register inclusive cumsum.
    float m = v[0];
    #pragma unroll
    for (int k = 1; k < SROWS; k++) m = fmaxf(m, v[k]);
    float run = 0.0f;
    #pragma unroll
    for (int k = 0; k < SROWS; k++) {
        run += __expf(v[k] - m);
        v[k] = run;                 // v[k] now holds S_k (inclusive cumsum)
    }
    sm_v[w][lc] = m + __logf(run);  // chunk logsumexp
    __syncthreads();

    // ---- Phase 2: warp 0 scans the 8 chunk totals + cross-segment carry.
    if (threadIdx.x < 32) {
        float cv[NW];
        #pragma unroll
        for (int j = 0; j < NW; j++) cv[j] = sm_v[j][lc];
        float mm = cv[0];
        #pragma unroll
        for (int j = 1; j < NW; j++) mm = fmaxf(mm, cv[j]);
        float cpre[NW], csum = 0.0f;
        #pragma unroll
        for (int j = 0; j < NW; j++) {
            cpre[j] = csum;                  // exclusive cumsum in exp domain
            csum += __expf(cv[j] - mm);
        }

        float excl;
        if (seg == 0) {
            excl = -CUDART_INF_F;
        } else {
            unsigned long long u = early;
            while ((u >> 32) == 0ULL) {
                u = poll_cg(pred_slot);
                if ((u >> 32) != 0ULL) break;
                __nanosleep(32);             // back off: keep pollers off L2
            }
            excl = __uint_as_float((unsigned)u);
        }

        const float M  = fmaxf(excl, mm);
        const float Ea = __expf(excl - M);   // 0 when excl == -inf
        const float Eb = __expf(mm - M);

        // Publish this segment's inclusive prefix (single atomic 8B word).
        const float inc = M + __logf(Ea + Eb * csum);
        unsigned long long pub =
            (1ULL << 32) | (unsigned long long)__float_as_uint(inc);
        __stcg(&g_slot[((size_t)chain * NSEG + seg) * CT + lc], pub);

        // Per-chunk log-domain exclusive prefixes (cpre[0]=0, Ea=0 -> -inf ok).
        #pragma unroll
        for (int j = 0; j < NW; j++)
            sm_p[j][lc] = M + __logf(Ea + Eb * cpre[j]);
    }
    __syncthreads();

    // ---- Phase 3: seeded emit — independent LG2 per element, no serial chain.
    const float acc = sm_p[w][lc];
    const float M2  = fmaxf(acc, m);       // m is finite, so M2 > -inf
    const float Ea2 = __expf(acc - M2);    // 0 when acc == -inf
    const float Eb2 = __expf(m - M2);
    #pragma unroll
    for (int k = 0; k < SROWS; k++) {
        float r = M2 + __logf(fmaf(Eb2, v[k], Ea2));
        __stcs(op + (size_t)k * CC, r);
    }
}

extern "C" void kernel_launch(void* const* d_in, const int* in_sizes, int n_in,
                              void* d_out, int out_size) {
    const float* x = (const float*)d_in[0];
    float* out = (float*)d_out;
    (void)in_sizes; (void)n_in; (void)out_size;

    zero_slots_kernel<<<(NSLOT + 255) / 256, 256>>>();
    lcse_seg_kernel<<<NBLK, 256>>>(x, out);
}